// round 15
// baseline (speedup 1.0000x reference)
#include <cuda_runtime.h>
#include <cuda_fp16.h>
#include <cstdint>
#include <math.h>

// Problem dims
#define BB 8192
#define DD 256
#define HH 512
#define KK 1280   // D + 2H
#define NN 2560   // 5H

// GEMM tiling: CTA 64(M) x 160(N'), N' interleaved as n' = j*5 + g.
// 8 warps (2M x 4N), warp tile 32x40 (mi=2, ni=5). fp16 mma.sync m16n8k16.
#define BM 64
#define BN 160
#define BKH 64          // K per stage
#define NT (KK / BKH)   // 20
#define STRH 72         // padded smem row stride in halves
#define STRB 144        // row stride bytes
#define STAGE_BYTES ((BM + BN) * STRB)          // 32256
#define SMEM_BYTES  (2 * STAGE_BYTES)           // 64512 (also covers sg: 64*164*4=41984)
#define SGS 164         // fp32 gate-staging row stride (words)

// Scratch (device globals; allocation is forbidden)
__device__ __half g_Ah[(size_t)BB * KK];     // A = [x|h_t|h_s] fp16   [8192,1280]
__device__ __half g_WTh[(size_t)NN * KK];    // W^T fp16, rows n'=j*5+g [2560,1280]
__device__ float  g_bias[NN];                // bias in n' order

// ---------------------------------------------------------------------------
__device__ __forceinline__ void cp_async16_s(uint32_t saddr, const void* g) {
    asm volatile("cp.async.cg.shared.global [%0], [%1], 16;" :: "r"(saddr), "l"(g));
}
__device__ __forceinline__ uint32_t smem_to_u32(const void* p) {
    uint32_t a;
    asm("{ .reg .u64 t; cvta.to.shared.u64 t, %1; cvt.u32.u64 %0, t; }" : "=r"(a) : "l"(p));
    return a;
}
__device__ __forceinline__ float sigmoid_f(float x) {
    return 1.0f / (1.0f + __expf(-x));
}
__device__ __forceinline__ float tanh_f(float x) {
    return 2.0f / (1.0f + __expf(-2.0f * x)) - 1.0f;
}
__device__ __forceinline__ void ldsm_x4(uint32_t r[4], uint32_t addr) {
    asm volatile("ldmatrix.sync.aligned.m8n8.x4.shared.b16 {%0,%1,%2,%3}, [%4];"
                 : "=r"(r[0]), "=r"(r[1]), "=r"(r[2]), "=r"(r[3]) : "r"(addr));
}
__device__ __forceinline__ void ldsm_x2(uint32_t r[2], uint32_t addr) {
    asm volatile("ldmatrix.sync.aligned.m8n8.x2.shared.b16 {%0,%1}, [%2];"
                 : "=r"(r[0]), "=r"(r[1]) : "r"(addr));
}
__device__ __forceinline__ void mma_f16(float c[4], const uint32_t a[4],
                                        uint32_t b0, uint32_t b1) {
    asm volatile(
        "mma.sync.aligned.m16n8k16.row.col.f32.f16.f16.f32 "
        "{%0,%1,%2,%3}, {%4,%5,%6,%7}, {%8,%9}, {%0,%1,%2,%3};"
        : "+f"(c[0]), "+f"(c[1]), "+f"(c[2]), "+f"(c[3])
        : "r"(a[0]), "r"(a[1]), "r"(a[2]), "r"(a[3]),
          "r"(b0), "r"(b1));
}

// ---------------------------------------------------------------------------
// pack_A: A = [x | h_t | h_s] -> fp16. Each thread converts 4 elements.
// ---------------------------------------------------------------------------
__global__ void pack_A_kernel(const float* __restrict__ x,
                              const float* __restrict__ ht,
                              const float* __restrict__ hs) {
    int idx = blockIdx.x * blockDim.x + threadIdx.x;
    const int total = BB * KK / 4;
    if (idx >= total) return;
    int b  = idx / (KK / 4);
    int k4 = (idx % (KK / 4)) * 4;
    float4 v;
    if (k4 < DD)              v = *(const float4*)(x  + (size_t)b * DD + k4);
    else if (k4 < DD + HH)    v = *(const float4*)(ht + (size_t)b * HH + (k4 - DD));
    else                      v = *(const float4*)(hs + (size_t)b * HH + (k4 - DD - HH));
    __half2 lo = __floats2half2_rn(v.x, v.y);
    __half2 hi = __floats2half2_rn(v.z, v.w);
    uint2 packed = make_uint2(*(uint32_t*)&lo, *(uint32_t*)&hi);
    *(uint2*)(g_Ah + (size_t)b * KK + k4) = packed;
}

// ---------------------------------------------------------------------------
// pack_WT: WT[n'][k] with n' = j*5 + g, from concat-W[k][g*512+j]. + bias (n' order).
// ---------------------------------------------------------------------------
__global__ void pack_WT_kernel(
    const float* Ui, const float* Us, const float* Ut, const float* Uo, const float* Uc,
    const float* Wti, const float* Wts, const float* Wtt, const float* Wto, const float* Wtc,
    const float* Wsi, const float* Wss, const float* Wst, const float* Wso, const float* Wsc,
    const float* bi, const float* bs, const float* bt, const float* bo, const float* bc) {
    __shared__ float t[32][33];
    const float* Ua[5]  = {Ui, Us, Ut, Uo, Uc};
    const float* Wta[5] = {Wti, Wts, Wtt, Wto, Wtc};
    const float* Wsa[5] = {Wsi, Wss, Wst, Wso, Wsc};

    int kb = blockIdx.x * 32;   // K block
    int nb = blockIdx.y * 32;   // source-N block (gate-major space)
#pragma unroll
    for (int i = 0; i < 4; i++) {
        int k = kb + threadIdx.y + i * 8;
        int n = nb + threadIdx.x;
        int g = n >> 9, j = n & 511;
        const float* src; int kk;
        if (k < DD)           { src = Ua[g];  kk = k; }
        else if (k < DD + HH) { src = Wta[g]; kk = k - DD; }
        else                  { src = Wsa[g]; kk = k - DD - HH; }
        t[threadIdx.y + i * 8][threadIdx.x] = src[(size_t)kk * HH + j];
    }
    __syncthreads();
#pragma unroll
    for (int i = 0; i < 4; i++) {
        int n = nb + threadIdx.y + i * 8;
        int k = kb + threadIdx.x;
        int g = n >> 9, j = n & 511;
        int nprime = j * 5 + g;
        g_WTh[(size_t)nprime * KK + k] = __float2half_rn(t[threadIdx.x][threadIdx.y + i * 8]);
    }
    if (blockIdx.x == 0 && blockIdx.y == 0) {
        const float* ba[5] = {bi, bs, bt, bo, bc};
        int tid = threadIdx.y * 32 + threadIdx.x;
        for (int idx = tid; idx < NN; idx += 256) {
            int g = idx >> 9, j = idx & 511;
            g_bias[j * 5 + g] = ba[g][j];
        }
    }
}

// ---------------------------------------------------------------------------
// Fused GEMM + activation + LSTM combine.
// gates = act(A @ W + b); c_h = i*c_n + f_t*c_t + f_s*c_s; h = o*tanh(c_h)
// out = [h ; c_h]. One CTA owns all 5 gates for a 32-wide j slice.
// ---------------------------------------------------------------------------
__global__ void __launch_bounds__(256, 2)
gemm_lstm_kernel(const float* __restrict__ ct,
                 const float* __restrict__ cs,
                 float* __restrict__ out) {
    extern __shared__ __half smem[];
    uint32_t sbase = smem_to_u32(smem);

    const int tid  = threadIdx.x;
    const int warp = tid >> 5;
    const int lane = tid & 31;
    const int wm = warp >> 2;     // 0..1  (M)
    const int wn = warp & 3;      // 0..3  (N)
    const int lr = lane >> 2;     // 0..7
    const int lc = lane & 3;      // 0..3
    const int l7 = lane & 7;

    const int brow  = blockIdx.y * BM;       // M offset
    const int tcol  = blockIdx.x;            // j-slice index (j in [tcol*32, tcol*32+32))
    const int bcoln = tcol * BN;             // n' offset

    // ldmatrix per-lane byte offsets
    const uint32_t offA = (uint32_t)(wm * 32 + l7 + ((lane >> 3) & 1) * 8) * STRB
                        + ((lane >> 4) & 1) * 16;
    const uint32_t offB = (uint32_t)(wn * 40 + l7 + ((lane >> 4) & 1) * 8) * STRB
                        + ((lane >> 3) & 1) * 16;
    const uint32_t offB2 = (uint32_t)(wn * 40 + 32 + l7) * STRB
                        + ((lane >> 3) & 1) * 16;   // x2: lanes 0-15 used

    float acc[2][5][4];
#pragma unroll
    for (int mi = 0; mi < 2; mi++)
#pragma unroll
        for (int ni = 0; ni < 5; ni++)
#pragma unroll
            for (int q = 0; q < 4; q++) acc[mi][ni][q] = 0.f;

    const __half* Agb = g_Ah  + (size_t)brow * KK;
    const __half* Bgb = g_WTh + (size_t)bcoln * KK;

    // A: 64 rows x 8 chunks = 512; B: 160 rows x 8 chunks = 1280; total 1792 = 7*256
    auto load_tile = [&](int kt, int stage) {
        uint32_t sA = sbase + stage * STAGE_BYTES;
        uint32_t sB = sA + BM * STRB;
        int kbase = kt * BKH;
#pragma unroll
        for (int p = 0; p < 7; p++) {
            int id = p * 256 + tid;
            if (id < 512) {
                int r = id >> 3, c = id & 7;
                cp_async16_s(sA + r * STRB + c * 16,
                             Agb + (size_t)r * KK + kbase + c * 8);
            } else {
                int id2 = id - 512;
                int r = id2 >> 3, c = id2 & 7;
                cp_async16_s(sB + r * STRB + c * 16,
                             Bgb + (size_t)r * KK + kbase + c * 8);
            }
        }
        asm volatile("cp.async.commit_group;" ::: "memory");
    };

    load_tile(0, 0);
    asm volatile("cp.async.wait_group 0;" ::: "memory");
    __syncthreads();

    for (int kt = 0; kt < NT; kt++) {
        if (kt + 1 < NT) load_tile(kt + 1, (kt + 1) & 1);

        uint32_t sA = sbase + (kt & 1) * STAGE_BYTES;
        uint32_t sB = sA + BM * STRB;

#pragma unroll
        for (int kk = 0; kk < 4; kk++) {
            const uint32_t kb = kk * 32;
            uint32_t a[2][4];
#pragma unroll
            for (int mi = 0; mi < 2; mi++)
                ldsm_x4(a[mi], sA + offA + mi * 16 * STRB + kb);

            uint32_t b0[5], b1[5];
#pragma unroll
            for (int q = 0; q < 2; q++) {
                uint32_t r[4];
                ldsm_x4(r, sB + offB + q * 16 * STRB + kb);
                b0[2 * q]     = r[0];  b1[2 * q]     = r[1];
                b0[2 * q + 1] = r[2];  b1[2 * q + 1] = r[3];
            }
            {
                uint32_t r2[2];
                ldsm_x2(r2, sB + offB2 + kb);
                b0[4] = r2[0];  b1[4] = r2[1];
            }
#pragma unroll
            for (int mi = 0; mi < 2; mi++)
#pragma unroll
                for (int ni = 0; ni < 5; ni++)
                    mma_f16(acc[mi][ni], a[mi], b0[ni], b1[ni]);
        }
        asm volatile("cp.async.wait_group 0;" ::: "memory");
        __syncthreads();
    }

    // ---- Epilogue phase 1: bias + activation -> fp32 gate staging in smem ----
    __syncthreads();   // all warps done reading stage buffers
    float* sg = (float*)smem;   // [64][SGS] fp32, reuses pipeline smem
#pragma unroll
    for (int mi = 0; mi < 2; mi++) {
        int r0 = wm * 32 + mi * 16 + lr;
#pragma unroll
        for (int ni = 0; ni < 5; ni++) {
            int nl = wn * 40 + ni * 8 + lc * 2;
            float bb0 = g_bias[bcoln + nl];
            float bb1 = g_bias[bcoln + nl + 1];
            float v0 = acc[mi][ni][0] + bb0;
            float v1 = acc[mi][ni][1] + bb1;
            float v2 = acc[mi][ni][2] + bb0;
            float v3 = acc[mi][ni][3] + bb1;
            // gate id = n' % 5 ; tanh for gate 4 (c), sigmoid otherwise
            bool t0 = (nl % 5) == 4;
            bool t1 = ((nl + 1) % 5) == 4;
            v0 = t0 ? tanh_f(v0) : sigmoid_f(v0);
            v1 = t1 ? tanh_f(v1) : sigmoid_f(v1);
            v2 = t0 ? tanh_f(v2) : sigmoid_f(v2);
            v3 = t1 ? tanh_f(v3) : sigmoid_f(v3);
            sg[r0 * SGS + nl]           = v0;
            sg[r0 * SGS + nl + 1]       = v1;
            sg[(r0 + 8) * SGS + nl]     = v2;
            sg[(r0 + 8) * SGS + nl + 1] = v3;
        }
    }
    __syncthreads();

    // ---- Epilogue phase 2: combine. warp w handles rows w*8..w*8+7, lane = jl ----
#pragma unroll
    for (int it = 0; it < 8; it++) {
        int row = warp * 8 + it;
        int jl  = lane;
        const float* sr = sg + row * SGS + jl * 5;
        float gi = sr[0];   // i      (sigmoid)
        float fs = sr[1];   // f_s    (sigmoid)
        float ft = sr[2];   // f_t    (sigmoid)
        float go = sr[3];   // o      (sigmoid)
        float cn = sr[4];   // c_n    (tanh)
        int bg  = brow + row;
        int col = tcol * 32 + jl;
        float ctv = ct[(size_t)bg * HH + col];
        float csv = cs[(size_t)bg * HH + col];
        float ch = gi * cn + ft * ctv + fs * csv;
        float h  = go * tanh_f(ch);
        out[(size_t)bg * HH + col] = h;
        out[(size_t)BB * HH + (size_t)bg * HH + col] = ch;
    }
}

// ---------------------------------------------------------------------------
extern "C" void kernel_launch(void* const* d_in, const int* in_sizes, int n_in,
                              void* d_out, int out_size) {
    const float* x   = (const float*)d_in[0];
    const float* h_t = (const float*)d_in[1];
    const float* h_s = (const float*)d_in[2];
    const float* c_t = (const float*)d_in[3];
    const float* c_s = (const float*)d_in[4];
    const float* Ui  = (const float*)d_in[5];
    const float* Wti = (const float*)d_in[6];
    const float* Wsi = (const float*)d_in[7];
    const float* bi  = (const float*)d_in[8];
    const float* Us  = (const float*)d_in[9];
    const float* Wts = (const float*)d_in[10];
    const float* Wss = (const float*)d_in[11];
    const float* bs  = (const float*)d_in[12];
    const float* Ut  = (const float*)d_in[13];
    const float* Wtt = (const float*)d_in[14];
    const float* Wst = (const float*)d_in[15];
    const float* bt  = (const float*)d_in[16];
    const float* Uo  = (const float*)d_in[17];
    const float* Wto = (const float*)d_in[18];
    const float* Wso = (const float*)d_in[19];
    const float* bo  = (const float*)d_in[20];
    const float* Uc  = (const float*)d_in[21];
    const float* Wtc = (const float*)d_in[22];
    const float* Wsc = (const float*)d_in[23];
    const float* bc  = (const float*)d_in[24];
    float* out = (float*)d_out;

    // pack A (fp16)
    {
        int total = BB * KK / 4;
        pack_A_kernel<<<(total + 255) / 256, 256>>>(x, h_t, h_s);
    }
    // pack W^T (fp16, interleaved n' = j*5+g) + bias
    {
        dim3 grid(KK / 32, NN / 32);   // (40, 80)
        pack_WT_kernel<<<grid, dim3(32, 8)>>>(
            Ui, Us, Ut, Uo, Uc,
            Wti, Wts, Wtt, Wto, Wtc,
            Wsi, Wss, Wst, Wso, Wsc,
            bi, bs, bt, bo, bc);
    }
    // fused GEMM + activation + combine
    {
        cudaFuncSetAttribute(gemm_lstm_kernel,
                             cudaFuncAttributeMaxDynamicSharedMemorySize, SMEM_BYTES);
        dim3 grid(HH / 32, BB / BM);   // (16, 128)
        gemm_lstm_kernel<<<grid, 256, SMEM_BYTES>>>(c_t, c_s, out);
    }
}

// round 16
// speedup vs baseline: 1.0057x; 1.0057x over previous
#include <cuda_runtime.h>
#include <cuda_fp16.h>
#include <cstdint>
#include <math.h>

// Problem dims
#define BB 8192
#define DD 256
#define HH 512
#define KK 1280   // D + 2H
#define NN 2560   // 5H

// GEMM tiling: CTA 64(M) x 160(N'), N' interleaved as n' = j*5 + g.
// 8 warps (2M x 4N), warp tile 32x40 (mi=2, ni=5). fp16 mma.sync m16n8k16.
#define BM 64
#define BN 160
#define BKH 64          // K per stage
#define NT (KK / BKH)   // 20
#define STRH 72         // padded smem row stride in halves
#define STRB 144        // row stride bytes
#define STAGE_BYTES ((BM + BN) * STRB)          // 32256
#define SMEM_BYTES  (2 * STAGE_BYTES)           // 64512 (also covers sg: 64*164*4=41984)
#define SGS 164         // fp32 gate-staging row stride (words)

// Scratch (device globals; allocation is forbidden)
__device__ __half g_Ah[(size_t)BB * KK];     // A = [x|h_t|h_s] fp16   [8192,1280]
__device__ __half g_WTh[(size_t)NN * KK];    // W^T fp16, rows n'=j*5+g [2560,1280]
__device__ float  g_bias[NN];                // bias in n' order

// ---------------------------------------------------------------------------
__device__ __forceinline__ void cp_async16_s(uint32_t saddr, const void* g) {
    asm volatile("cp.async.cg.shared.global [%0], [%1], 16;" :: "r"(saddr), "l"(g));
}
__device__ __forceinline__ uint32_t smem_to_u32(const void* p) {
    uint32_t a;
    asm("{ .reg .u64 t; cvta.to.shared.u64 t, %1; cvt.u32.u64 %0, t; }" : "=r"(a) : "l"(p));
    return a;
}
__device__ __forceinline__ float sigmoid_f(float x) {
    return 1.0f / (1.0f + __expf(-x));
}
__device__ __forceinline__ float tanh_f(float x) {
    return 2.0f / (1.0f + __expf(-2.0f * x)) - 1.0f;
}
__device__ __forceinline__ void ldsm_x4(uint32_t r[4], uint32_t addr) {
    asm volatile("ldmatrix.sync.aligned.m8n8.x4.shared.b16 {%0,%1,%2,%3}, [%4];"
                 : "=r"(r[0]), "=r"(r[1]), "=r"(r[2]), "=r"(r[3]) : "r"(addr));
}
__device__ __forceinline__ void ldsm_x2(uint32_t r[2], uint32_t addr) {
    asm volatile("ldmatrix.sync.aligned.m8n8.x2.shared.b16 {%0,%1}, [%2];"
                 : "=r"(r[0]), "=r"(r[1]) : "r"(addr));
}
__device__ __forceinline__ void mma_f16(float c[4], const uint32_t a[4],
                                        uint32_t b0, uint32_t b1) {
    asm volatile(
        "mma.sync.aligned.m16n8k16.row.col.f32.f16.f16.f32 "
        "{%0,%1,%2,%3}, {%4,%5,%6,%7}, {%8,%9}, {%0,%1,%2,%3};"
        : "+f"(c[0]), "+f"(c[1]), "+f"(c[2]), "+f"(c[3])
        : "r"(a[0]), "r"(a[1]), "r"(a[2]), "r"(a[3]),
          "r"(b0), "r"(b1));
}

// ---------------------------------------------------------------------------
// pack_A: A = [x | h_t | h_s] -> fp16. Each thread converts 4 elements.
// ---------------------------------------------------------------------------
__global__ void pack_A_kernel(const float* __restrict__ x,
                              const float* __restrict__ ht,
                              const float* __restrict__ hs) {
    int idx = blockIdx.x * blockDim.x + threadIdx.x;
    const int total = BB * KK / 4;
    if (idx >= total) return;
    int b  = idx / (KK / 4);
    int k4 = (idx % (KK / 4)) * 4;
    float4 v;
    if (k4 < DD)              v = *(const float4*)(x  + (size_t)b * DD + k4);
    else if (k4 < DD + HH)    v = *(const float4*)(ht + (size_t)b * HH + (k4 - DD));
    else                      v = *(const float4*)(hs + (size_t)b * HH + (k4 - DD - HH));
    __half2 lo = __floats2half2_rn(v.x, v.y);
    __half2 hi = __floats2half2_rn(v.z, v.w);
    uint2 packed = make_uint2(*(uint32_t*)&lo, *(uint32_t*)&hi);
    *(uint2*)(g_Ah + (size_t)b * KK + k4) = packed;
}

// ---------------------------------------------------------------------------
// pack_WT: WT[n'][k] with n' = j*5 + g, from concat-W[k][g*512+j]. + bias (n' order).
// ---------------------------------------------------------------------------
__global__ void pack_WT_kernel(
    const float* Ui, const float* Us, const float* Ut, const float* Uo, const float* Uc,
    const float* Wti, const float* Wts, const float* Wtt, const float* Wto, const float* Wtc,
    const float* Wsi, const float* Wss, const float* Wst, const float* Wso, const float* Wsc,
    const float* bi, const float* bs, const float* bt, const float* bo, const float* bc) {
    __shared__ float t[32][33];
    const float* Ua[5]  = {Ui, Us, Ut, Uo, Uc};
    const float* Wta[5] = {Wti, Wts, Wtt, Wto, Wtc};
    const float* Wsa[5] = {Wsi, Wss, Wst, Wso, Wsc};

    int kb = blockIdx.x * 32;   // K block
    int nb = blockIdx.y * 32;   // source-N block (gate-major space)
#pragma unroll
    for (int i = 0; i < 4; i++) {
        int k = kb + threadIdx.y + i * 8;
        int n = nb + threadIdx.x;
        int g = n >> 9, j = n & 511;
        const float* src; int kk;
        if (k < DD)           { src = Ua[g];  kk = k; }
        else if (k < DD + HH) { src = Wta[g]; kk = k - DD; }
        else                  { src = Wsa[g]; kk = k - DD - HH; }
        t[threadIdx.y + i * 8][threadIdx.x] = src[(size_t)kk * HH + j];
    }
    __syncthreads();
#pragma unroll
    for (int i = 0; i < 4; i++) {
        int n = nb + threadIdx.y + i * 8;
        int k = kb + threadIdx.x;
        int g = n >> 9, j = n & 511;
        int nprime = j * 5 + g;
        g_WTh[(size_t)nprime * KK + k] = __float2half_rn(t[threadIdx.x][threadIdx.y + i * 8]);
    }
    if (blockIdx.x == 0 && blockIdx.y == 0) {
        const float* ba[5] = {bi, bs, bt, bo, bc};
        int tid = threadIdx.y * 32 + threadIdx.x;
        for (int idx = tid; idx < NN; idx += 256) {
            int g = idx >> 9, j = idx & 511;
            g_bias[j * 5 + g] = ba[g][j];
        }
    }
}

// ---------------------------------------------------------------------------
// Fused GEMM + activation + LSTM combine.
// gates = act(A @ W + b); c_h = i*c_n + f_t*c_t + f_s*c_s; h = o*tanh(c_h)
// out = [h ; c_h]. One CTA owns all 5 gates for a 32-wide j slice.
// ---------------------------------------------------------------------------
__global__ void __launch_bounds__(256, 2)
gemm_lstm_kernel(const float* __restrict__ ct,
                 const float* __restrict__ cs,
                 float* __restrict__ out) {
    extern __shared__ __half smem[];
    uint32_t sbase = smem_to_u32(smem);

    const int tid  = threadIdx.x;
    const int warp = tid >> 5;
    const int lane = tid & 31;
    const int wm = warp >> 2;     // 0..1  (M)
    const int wn = warp & 3;      // 0..3  (N)
    const int lr = lane >> 2;     // 0..7
    const int lc = lane & 3;      // 0..3
    const int l7 = lane & 7;

    const int brow  = blockIdx.y * BM;       // M offset
    const int tcol  = blockIdx.x;            // j-slice index (j in [tcol*32, tcol*32+32))
    const int bcoln = tcol * BN;             // n' offset

    // ldmatrix per-lane byte offsets
    const uint32_t offA = (uint32_t)(wm * 32 + l7 + ((lane >> 3) & 1) * 8) * STRB
                        + ((lane >> 4) & 1) * 16;
    const uint32_t offB = (uint32_t)(wn * 40 + l7 + ((lane >> 4) & 1) * 8) * STRB
                        + ((lane >> 3) & 1) * 16;
    const uint32_t offB2 = (uint32_t)(wn * 40 + 32 + l7) * STRB
                        + ((lane >> 3) & 1) * 16;   // x2: lanes 0-15 used

    float acc[2][5][4];
#pragma unroll
    for (int mi = 0; mi < 2; mi++)
#pragma unroll
        for (int ni = 0; ni < 5; ni++)
#pragma unroll
            for (int q = 0; q < 4; q++) acc[mi][ni][q] = 0.f;

    const __half* Agb = g_Ah  + (size_t)brow * KK;
    const __half* Bgb = g_WTh + (size_t)bcoln * KK;

    // A: 64 rows x 8 chunks = 512; B: 160 rows x 8 chunks = 1280; total 1792 = 7*256
    auto load_tile = [&](int kt, int stage) {
        uint32_t sA = sbase + stage * STAGE_BYTES;
        uint32_t sB = sA + BM * STRB;
        int kbase = kt * BKH;
#pragma unroll
        for (int p = 0; p < 7; p++) {
            int id = p * 256 + tid;
            if (id < 512) {
                int r = id >> 3, c = id & 7;
                cp_async16_s(sA + r * STRB + c * 16,
                             Agb + (size_t)r * KK + kbase + c * 8);
            } else {
                int id2 = id - 512;
                int r = id2 >> 3, c = id2 & 7;
                cp_async16_s(sB + r * STRB + c * 16,
                             Bgb + (size_t)r * KK + kbase + c * 8);
            }
        }
        asm volatile("cp.async.commit_group;" ::: "memory");
    };

    load_tile(0, 0);
    asm volatile("cp.async.wait_group 0;" ::: "memory");
    __syncthreads();

    for (int kt = 0; kt < NT; kt++) {
        if (kt + 1 < NT) load_tile(kt + 1, (kt + 1) & 1);

        uint32_t sA = sbase + (kt & 1) * STAGE_BYTES;
        uint32_t sB = sA + BM * STRB;

#pragma unroll
        for (int kk = 0; kk < 4; kk++) {
            const uint32_t kb = kk * 32;
            uint32_t a[2][4];
#pragma unroll
            for (int mi = 0; mi < 2; mi++)
                ldsm_x4(a[mi], sA + offA + mi * 16 * STRB + kb);

            uint32_t b0[5], b1[5];
#pragma unroll
            for (int q = 0; q < 2; q++) {
                uint32_t r[4];
                ldsm_x4(r, sB + offB + q * 16 * STRB + kb);
                b0[2 * q]     = r[0];  b1[2 * q]     = r[1];
                b0[2 * q + 1] = r[2];  b1[2 * q + 1] = r[3];
            }
            {
                uint32_t r2[2];
                ldsm_x2(r2, sB + offB2 + kb);
                b0[4] = r2[0];  b1[4] = r2[1];
            }
#pragma unroll
            for (int mi = 0; mi < 2; mi++)
#pragma unroll
                for (int ni = 0; ni < 5; ni++)
                    mma_f16(acc[mi][ni], a[mi], b0[ni], b1[ni]);
        }
        asm volatile("cp.async.wait_group 0;" ::: "memory");
        __syncthreads();
    }

    // ---- Epilogue phase 1: bias + activation -> fp32 gate staging in smem ----
    __syncthreads();   // all warps done reading stage buffers
    float* sg = (float*)smem;   // [64][SGS] fp32, reuses pipeline smem
#pragma unroll
    for (int mi = 0; mi < 2; mi++) {
        int r0 = wm * 32 + mi * 16 + lr;
#pragma unroll
        for (int ni = 0; ni < 5; ni++) {
            int nl = wn * 40 + ni * 8 + lc * 2;
            float bb0 = g_bias[bcoln + nl];
            float bb1 = g_bias[bcoln + nl + 1];
            float v0 = acc[mi][ni][0] + bb0;
            float v1 = acc[mi][ni][1] + bb1;
            float v2 = acc[mi][ni][2] + bb0;
            float v3 = acc[mi][ni][3] + bb1;
            // gate id = n' % 5 ; tanh for gate 4 (c), sigmoid otherwise
            bool t0 = (nl % 5) == 4;
            bool t1 = ((nl + 1) % 5) == 4;
            v0 = t0 ? tanh_f(v0) : sigmoid_f(v0);
            v1 = t1 ? tanh_f(v1) : sigmoid_f(v1);
            v2 = t0 ? tanh_f(v2) : sigmoid_f(v2);
            v3 = t1 ? tanh_f(v3) : sigmoid_f(v3);
            sg[r0 * SGS + nl]           = v0;
            sg[r0 * SGS + nl + 1]       = v1;
            sg[(r0 + 8) * SGS + nl]     = v2;
            sg[(r0 + 8) * SGS + nl + 1] = v3;
        }
    }
    __syncthreads();

    // ---- Epilogue phase 2: combine. warp w handles rows w*8..w*8+7, lane = jl ----
#pragma unroll
    for (int it = 0; it < 8; it++) {
        int row = warp * 8 + it;
        int jl  = lane;
        const float* sr = sg + row * SGS + jl * 5;
        float gi = sr[0];   // i      (sigmoid)
        float fs = sr[1];   // f_s    (sigmoid)
        float ft = sr[2];   // f_t    (sigmoid)
        float go = sr[3];   // o      (sigmoid)
        float cn = sr[4];   // c_n    (tanh)
        int bg  = brow + row;
        int col = tcol * 32 + jl;
        float ctv = ct[(size_t)bg * HH + col];
        float csv = cs[(size_t)bg * HH + col];
        float ch = gi * cn + ft * ctv + fs * csv;
        float h  = go * tanh_f(ch);
        out[(size_t)bg * HH + col] = h;
        out[(size_t)BB * HH + (size_t)bg * HH + col] = ch;
    }
}

// ---------------------------------------------------------------------------
extern "C" void kernel_launch(void* const* d_in, const int* in_sizes, int n_in,
                              void* d_out, int out_size) {
    const float* x   = (const float*)d_in[0];
    const float* h_t = (const float*)d_in[1];
    const float* h_s = (const float*)d_in[2];
    const float* c_t = (const float*)d_in[3];
    const float* c_s = (const float*)d_in[4];
    const float* Ui  = (const float*)d_in[5];
    const float* Wti = (const float*)d_in[6];
    const float* Wsi = (const float*)d_in[7];
    const float* bi  = (const float*)d_in[8];
    const float* Us  = (const float*)d_in[9];
    const float* Wts = (const float*)d_in[10];
    const float* Wss = (const float*)d_in[11];
    const float* bs  = (const float*)d_in[12];
    const float* Ut  = (const float*)d_in[13];
    const float* Wtt = (const float*)d_in[14];
    const float* Wst = (const float*)d_in[15];
    const float* bt  = (const float*)d_in[16];
    const float* Uo  = (const float*)d_in[17];
    const float* Wto = (const float*)d_in[18];
    const float* Wso = (const float*)d_in[19];
    const float* bo  = (const float*)d_in[20];
    const float* Uc  = (const float*)d_in[21];
    const float* Wtc = (const float*)d_in[22];
    const float* Wsc = (const float*)d_in[23];
    const float* bc  = (const float*)d_in[24];
    float* out = (float*)d_out;

    // pack A (fp16)
    {
        int total = BB * KK / 4;
        pack_A_kernel<<<(total + 255) / 256, 256>>>(x, h_t, h_s);
    }
    // pack W^T (fp16, interleaved n' = j*5+g) + bias
    {
        dim3 grid(KK / 32, NN / 32);   // (40, 80)
        pack_WT_kernel<<<grid, dim3(32, 8)>>>(
            Ui, Us, Ut, Uo, Uc,
            Wti, Wts, Wtt, Wto, Wtc,
            Wsi, Wss, Wst, Wso, Wsc,
            bi, bs, bt, bo, bc);
    }
    // fused GEMM + activation + combine
    {
        cudaFuncSetAttribute(gemm_lstm_kernel,
                             cudaFuncAttributeMaxDynamicSharedMemorySize, SMEM_BYTES);
        dim3 grid(HH / 32, BB / BM);   // (16, 128)
        gemm_lstm_kernel<<<grid, 256, SMEM_BYTES>>>(c_t, c_s, out);
    }
}